// round 15
// baseline (speedup 1.0000x reference)
#include <cuda_runtime.h>
#include <cuda_fp16.h>
#include <cstdint>

// ============================================================================
// Fused LatentDynamicsModel, single-pass fp16 mma.sync (family-common PTX).
// R15: 8 warps x (32x64) tiles @ 256 threads, 2 CTAs/SM (independent barrier
// domains), hn in thread-private global scratch (L2-resident), direct global
// epilogue stores (no smem TO staging).
// ============================================================================

#define TM      64
#define THREADS 256
#define BATCH   131072
#define LDA     264      // fp16 elems, activation tile stride (528B rows)

// ---- pre-converted fp16 weights (row-major [N][K], W_in padded K66->128) ----
#define OFF_WIN 0
#define OFF_WIH (OFF_WIN + 256 * 128)
#define OFF_WHH (OFF_WIH + 768 * 256)
#define OFF_WO1 (OFF_WHH + 768 * 256)
#define OFF_WO2 (OFF_WO1 + 256 * 256)
#define W_TOTAL (OFF_WO2 + 64 * 256)

__device__ __align__(16) __half g_W[W_TOTAL];
__device__ float g_HN[(long)BATCH * 256];   // hn scratch (thread-private use)

// ---- smem byte offsets ----
#define OFF_XH  0                 // 64 x 264 x 2B = 33792
#define OFF_HH  33792
#define OFF_W   67584             // 2 stages x (256 rows x 80B)
#define WSTAGE  20480
#define SMEM_TOTAL (67584 + 2 * WSTAGE)   // 108544 -> 2 CTAs/SM

__device__ __forceinline__ uint32_t smem_to_u32(const void* p) {
    uint32_t a;
    asm("{ .reg .u64 t; cvta.to.shared.u64 t, %1; cvt.u32.u64 %0, t; }"
        : "=r"(a) : "l"(p));
    return a;
}
__device__ __forceinline__ void ldsm4(uint32_t* r, uint32_t addr) {
    asm volatile("ldmatrix.sync.aligned.m8n8.x4.shared.b16 {%0,%1,%2,%3}, [%4];"
                 : "=r"(r[0]), "=r"(r[1]), "=r"(r[2]), "=r"(r[3]) : "r"(addr));
}
__device__ __forceinline__ void mma16816(float* d, const uint32_t* a, const uint32_t* b) {
    asm volatile("mma.sync.aligned.m16n8k16.row.col.f32.f16.f16.f32 "
                 "{%0,%1,%2,%3}, {%4,%5,%6,%7}, {%8,%9}, {%0,%1,%2,%3};"
                 : "+f"(d[0]), "+f"(d[1]), "+f"(d[2]), "+f"(d[3])
                 : "r"(a[0]), "r"(a[1]), "r"(a[2]), "r"(a[3]),
                   "r"(b[0]), "r"(b[1]));
}
__device__ __forceinline__ uint32_t pack2h(float x, float y) {
    __half2 h = __floats2half2_rn(x, y);
    return *reinterpret_cast<uint32_t*>(&h);
}
__device__ __forceinline__ float sigm(float x) { return 1.0f / (1.0f + __expf(-x)); }

// ======================= weight conversion kernel ===========================
__global__ void wconv_kernel(const float* __restrict__ W_in,
                             const float* __restrict__ W_ih,
                             const float* __restrict__ W_hh,
                             const float* __restrict__ W_o1,
                             const float* __restrict__ W_o2) {
    for (long i = (long)blockIdx.x * blockDim.x + threadIdx.x; i < W_TOTAL;
         i += (long)gridDim.x * blockDim.x) {
        float v;
        if (i < OFF_WIH)      { long r = i >> 7, c = i & 127;
                                v = (c < 66) ? W_in[r * 66 + c] : 0.0f; }
        else if (i < OFF_WHH)   v = W_ih[i - OFF_WIH];
        else if (i < OFF_WO1)   v = W_hh[i - OFF_WHH];
        else if (i < OFF_WO2)   v = W_o1[i - OFF_WO1];
        else                    v = W_o2[i - OFF_WO2];
        g_W[i] = __float2half_rn(v);
    }
}

// ---------------------------------------------------------------------------
// acc[2 mi][8 ni][4] += A(fp16 smem) @ W(fp16 global)^T
// Weight chunks [NR x 32] via 2-stage cp.async ping-pong.
// 8 warps, warp (warp_m, warp_n0): rows warp_m*32..+32, cols warp_n0..+64.
// ---------------------------------------------------------------------------
template <int NR>
__device__ void gemm_mma(float acc[2][8][4], uint32_t sb, uint32_t offA,
                         const __half* __restrict__ Wg, int ldw, int nchunks,
                         int tid, int lane, int warp_m, int warp_n0)
{
    constexpr int TOT   = NR * 4;                      // 16B transfers per chunk
    constexpr int NITER = (TOT + THREADS - 1) / THREADS;

    auto issue = [&](int c, int buf) {
        uint32_t base = sb + OFF_W + (uint32_t)buf * WSTAGE;
        #pragma unroll
        for (int it = 0; it < NITER; ++it) {
            int idx = tid + THREADS * it;
            if ((TOT % THREADS == 0) || (idx < TOT)) {
                int row = idx >> 2, q = idx & 3;
                const __half* src = Wg + (long)row * ldw + c * 32 + q * 8;
                uint32_t dst = base + row * 80 + q * 16;
                asm volatile("cp.async.ca.shared.global [%0], [%1], 16;"
                             :: "r"(dst), "l"(src));
            }
        }
        asm volatile("cp.async.commit_group;" ::: "memory");
    };

    issue(0, 0);
    for (int c = 0; c < nchunks; ++c) {
        asm volatile("cp.async.wait_group 0;" ::: "memory");
        __syncthreads();                // chunk c visible; prev compute done
        if (c + 1 < nchunks) issue(c + 1, (c + 1) & 1);

        const uint32_t wb = sb + OFF_W + (uint32_t)(c & 1) * WSTAGE;
        if (warp_n0 < NR) {
            const int mat = lane >> 3, r = lane & 7;
            #pragma unroll
            for (int ks = 0; ks < 2; ++ks) {
                uint32_t a[2][4], b[4][4];
                #pragma unroll
                for (int mi = 0; mi < 2; ++mi) {
                    int row = warp_m * 32 + mi * 16 + (mat & 1) * 8 + r;
                    int col = c * 32 + ks * 16 + (mat >> 1) * 8;
                    ldsm4(a[mi], sb + offA + (uint32_t)(row * LDA + col) * 2);
                }
                #pragma unroll
                for (int np = 0; np < 4; ++np) {
                    int n  = warp_n0 + (2 * np + (mat >> 1)) * 8 + r;
                    int kc = ks * 16 + (mat & 1) * 8;
                    ldsm4(b[np], wb + (uint32_t)(n * 80 + kc * 2));
                }
                #pragma unroll
                for (int np = 0; np < 4; ++np)
                    #pragma unroll
                    for (int hf = 0; hf < 2; ++hf)
                        #pragma unroll
                        for (int mi = 0; mi < 2; ++mi)
                            mma16816(acc[mi][2 * np + hf], a[mi], b[np] + 2 * hf);
            }
        }
    }
    __syncthreads();   // all mma reads of smem done before caller reuses tiles
}

__device__ __forceinline__ void zero_acc(float a[2][8][4]) {
    #pragma unroll
    for (int i = 0; i < 2; ++i)
        #pragma unroll
        for (int j = 0; j < 8; ++j)
            #pragma unroll
            for (int k = 0; k < 4; ++k) a[i][j][k] = 0.0f;
}

__global__ __launch_bounds__(THREADS, 2)
void ldm_kernel(const float* __restrict__ z, const float* __restrict__ action,
                const float* __restrict__ hidden,
                const float* __restrict__ b_in,
                const float* __restrict__ b_ih, const float* __restrict__ b_hh,
                const float* __restrict__ b_o1, const float* __restrict__ b_o2,
                float* __restrict__ out_z, float* __restrict__ out_h)
{
    extern __shared__ char sm[];
    const uint32_t sb = smem_to_u32(sm);
    const int tid = threadIdx.x, lane = tid & 31, warp = tid >> 5;
    const int warp_m = warp & 1, warp_n0 = (warp >> 1) * 64;
    const int gid = lane >> 2, tig = lane & 3;
    const long row0 = (long)blockIdx.x * TM;

    __half* XH = (__half*)(sm + OFF_XH);
    __half* HH = (__half*)(sm + OFF_HH);

    // ---- init: za = [z|action|0] -> X cols 0..127, hidden -> H ----
    for (int i = tid; i < TM * 128; i += THREADS) {
        int r = i >> 7, c = i & 127;
        float v = 0.0f;
        if (c < 64)      v = z[(row0 + r) * 64 + c];
        else if (c < 66) v = action[(row0 + r) * 2 + (c - 64)];
        XH[r * LDA + c] = __float2half_rn(v);
    }
    for (int i = tid; i < TM * 256; i += THREADS) {
        int r = i >> 8, c = i & 255;
        HH[r * LDA + c] = __float2half_rn(hidden[(row0 + r) * 256 + c]);
    }
    __syncthreads();

    float acc[2][8][4];

    // ================= P0: x = relu([z|a] @ W_in^T + b_in) =================
    zero_acc(acc);
    gemm_mma<256>(acc, sb, OFF_XH, g_W + OFF_WIN, 128, 4,
                  tid, lane, warp_m, warp_n0);
    #pragma unroll
    for (int mi = 0; mi < 2; ++mi)
        #pragma unroll
        for (int ni = 0; ni < 8; ++ni) {
            int col0 = warp_n0 + ni * 8 + tig * 2;
            int ra = warp_m * 32 + mi * 16 + gid, rb = ra + 8;
            float v0 = fmaxf(acc[mi][ni][0] + b_in[col0],     0.0f);
            float v1 = fmaxf(acc[mi][ni][1] + b_in[col0 + 1], 0.0f);
            float v2 = fmaxf(acc[mi][ni][2] + b_in[col0],     0.0f);
            float v3 = fmaxf(acc[mi][ni][3] + b_in[col0 + 1], 0.0f);
            *(uint32_t*)(sm + OFF_XH + (ra * LDA + col0) * 2) = pack2h(v0, v1);
            *(uint32_t*)(sm + OFF_XH + (rb * LDA + col0) * 2) = pack2h(v2, v3);
        }
    __syncthreads();

    // ================= P1: ghn = h @ Whh_n^T + b_hh_n =======================
    zero_acc(acc);
    gemm_mma<256>(acc, sb, OFF_HH, g_W + OFF_WHH + 512 * 256, 256, 8,
                  tid, lane, warp_m, warp_n0);
    #pragma unroll
    for (int mi = 0; mi < 2; ++mi)
        #pragma unroll
        for (int ni = 0; ni < 8; ++ni) {
            int col0 = warp_n0 + ni * 8 + tig * 2;
            int ra = warp_m * 32 + mi * 16 + gid, rb = ra + 8;
            g_HN[(row0 + ra) * 256 + col0]     = acc[mi][ni][0] + b_hh[512 + col0];
            g_HN[(row0 + ra) * 256 + col0 + 1] = acc[mi][ni][1] + b_hh[512 + col0 + 1];
            g_HN[(row0 + rb) * 256 + col0]     = acc[mi][ni][2] + b_hh[512 + col0];
            g_HN[(row0 + rb) * 256 + col0 + 1] = acc[mi][ni][3] + b_hh[512 + col0 + 1];
        }

    // ================= P2: r gate; ghn *= r =================================
    zero_acc(acc);
    gemm_mma<256>(acc, sb, OFF_XH, g_W + OFF_WIH, 256, 8,
                  tid, lane, warp_m, warp_n0);
    gemm_mma<256>(acc, sb, OFF_HH, g_W + OFF_WHH, 256, 8,
                  tid, lane, warp_m, warp_n0);
    #pragma unroll
    for (int mi = 0; mi < 2; ++mi)
        #pragma unroll
        for (int ni = 0; ni < 8; ++ni) {
            int col0 = warp_n0 + ni * 8 + tig * 2;
            int ra = warp_m * 32 + mi * 16 + gid, rb = ra + 8;
            #pragma unroll
            for (int cc = 0; cc < 4; ++cc) {
                int row = (cc < 2) ? ra : rb;
                int col = col0 + (cc & 1);
                float r_ = sigm(acc[mi][ni][cc] + b_ih[col] + b_hh[col]);
                g_HN[(row0 + row) * 256 + col] *= r_;
            }
        }

    // ================= P3: ghn = tanh(x@Wih_n + b + ghn) ====================
    zero_acc(acc);
    gemm_mma<256>(acc, sb, OFF_XH, g_W + OFF_WIH + 512 * 256, 256, 8,
                  tid, lane, warp_m, warp_n0);
    #pragma unroll
    for (int mi = 0; mi < 2; ++mi)
        #pragma unroll
        for (int ni = 0; ni < 8; ++ni) {
            int col0 = warp_n0 + ni * 8 + tig * 2;
            int ra = warp_m * 32 + mi * 16 + gid, rb = ra + 8;
            #pragma unroll
            for (int cc = 0; cc < 4; ++cc) {
                int row = (cc < 2) ? ra : rb;
                int col = col0 + (cc & 1);
                long idx = (row0 + row) * 256 + col;
                g_HN[idx] = tanhf(acc[mi][ni][cc] + b_ih[512 + col] + g_HN[idx]);
            }
        }

    // ================= P4: z gate; h_new -> out_h + XH ======================
    zero_acc(acc);
    gemm_mma<256>(acc, sb, OFF_XH, g_W + OFF_WIH + 256 * 256, 256, 8,
                  tid, lane, warp_m, warp_n0);
    gemm_mma<256>(acc, sb, OFF_HH, g_W + OFF_WHH + 256 * 256, 256, 8,
                  tid, lane, warp_m, warp_n0);
    #pragma unroll
    for (int mi = 0; mi < 2; ++mi)
        #pragma unroll
        for (int ni = 0; ni < 8; ++ni) {
            int col0 = warp_n0 + ni * 8 + tig * 2;
            int ra = warp_m * 32 + mi * 16 + gid, rb = ra + 8;
            float hv[4];
            #pragma unroll
            for (int cc = 0; cc < 4; ++cc) {
                int row = (cc < 2) ? ra : rb;
                int col = col0 + (cc & 1);
                long idx = (row0 + row) * 256 + col;
                float zg = sigm(acc[mi][ni][cc] + b_ih[256 + col] + b_hh[256 + col]);
                float h  = hidden[idx];
                hv[cc] = (1.0f - zg) * g_HN[idx] + zg * h;
                out_h[idx] = hv[cc];
            }
            *(uint32_t*)(sm + OFF_XH + (ra * LDA + col0) * 2) = pack2h(hv[0], hv[1]);
            *(uint32_t*)(sm + OFF_XH + (rb * LDA + col0) * 2) = pack2h(hv[2], hv[3]);
        }
    // XH writes published by the first __syncthreads inside the next gemm.

    // ================= P5: y = relu(h_new @ W_o1^T + b_o1) -> HH ============
    zero_acc(acc);
    gemm_mma<256>(acc, sb, OFF_XH, g_W + OFF_WO1, 256, 8,
                  tid, lane, warp_m, warp_n0);
    #pragma unroll
    for (int mi = 0; mi < 2; ++mi)
        #pragma unroll
        for (int ni = 0; ni < 8; ++ni) {
            int col0 = warp_n0 + ni * 8 + tig * 2;
            int ra = warp_m * 32 + mi * 16 + gid, rb = ra + 8;
            float v0 = fmaxf(acc[mi][ni][0] + b_o1[col0],     0.0f);
            float v1 = fmaxf(acc[mi][ni][1] + b_o1[col0 + 1], 0.0f);
            float v2 = fmaxf(acc[mi][ni][2] + b_o1[col0],     0.0f);
            float v3 = fmaxf(acc[mi][ni][3] + b_o1[col0 + 1], 0.0f);
            *(uint32_t*)(sm + OFF_HH + (ra * LDA + col0) * 2) = pack2h(v0, v1);
            *(uint32_t*)(sm + OFF_HH + (rb * LDA + col0) * 2) = pack2h(v2, v3);
        }

    // ================= P6: z_next = y @ W_o2^T + b_o2 (N=64) ================
    zero_acc(acc);
    gemm_mma<64>(acc, sb, OFF_HH, g_W + OFF_WO2, 256, 8,
                 tid, lane, warp_m, warp_n0);
    if (warp_n0 < 64) {
        #pragma unroll
        for (int mi = 0; mi < 2; ++mi)
            #pragma unroll
            for (int ni = 0; ni < 8; ++ni) {
                int col0 = warp_n0 + ni * 8 + tig * 2;
                int ra = warp_m * 32 + mi * 16 + gid, rb = ra + 8;
                out_z[(row0 + ra) * 64 + col0]     = acc[mi][ni][0] + b_o2[col0];
                out_z[(row0 + ra) * 64 + col0 + 1] = acc[mi][ni][1] + b_o2[col0 + 1];
                out_z[(row0 + rb) * 64 + col0]     = acc[mi][ni][2] + b_o2[col0];
                out_z[(row0 + rb) * 64 + col0 + 1] = acc[mi][ni][3] + b_o2[col0 + 1];
            }
    }
}

// ============================== launch ======================================

extern "C" void kernel_launch(void* const* d_in, const int* in_sizes, int n_in,
                              void* d_out, int out_size) {
    const float* z      = (const float*)d_in[0];
    const float* action = (const float*)d_in[1];
    const float* hidden = (const float*)d_in[2];
    const float* W_in   = (const float*)d_in[3];
    const float* b_in   = (const float*)d_in[4];
    const float* W_ih   = (const float*)d_in[5];
    const float* W_hh   = (const float*)d_in[6];
    const float* b_ih   = (const float*)d_in[7];
    const float* b_hh   = (const float*)d_in[8];
    const float* W_o1   = (const float*)d_in[9];
    const float* b_o1   = (const float*)d_in[10];
    const float* W_o2   = (const float*)d_in[11];
    const float* b_o2   = (const float*)d_in[12];

    float* out_z = (float*)d_out;                       // [B, 64]
    float* out_h = (float*)d_out + (long)BATCH * 64;    // [B, 256]

    cudaFuncSetAttribute(ldm_kernel,
                         cudaFuncAttributeMaxDynamicSharedMemorySize, SMEM_TOTAL);

    wconv_kernel<<<256, 256>>>(W_in, W_ih, W_hh, W_o1, W_o2);
    dim3 grid(BATCH / TM);
    ldm_kernel<<<grid, THREADS, SMEM_TOTAL>>>(
        z, action, hidden, b_in, b_ih, b_hh, b_o1, b_o2, out_z, out_h);
}

// round 16
// speedup vs baseline: 1.3071x; 1.3071x over previous
#include <cuda_runtime.h>
#include <cuda_fp16.h>
#include <cstdint>

// ============================================================================
// Fused LatentDynamicsModel, single-pass fp16 mma.sync (family-common PTX).
// R16: R14 machine (512 thr, 16 warps, 32x32 tiles, 4-stage cp.async) with
// half the sync points: 64-col K-chunks (34 chunk-barriers vs 68) and the
// r/z dual-GEMMs fused into single K=512 passes over a unified [X|H] tile
// (weights pre-concatenated), 9 -> 7 gemm calls.
// ============================================================================

#define TM      64
#define THREADS 512
#define BATCH   131072
#define LDA     520      // fp16 elems: cols 0..255 = X, 256..511 = H (1040B rows)
#define LDTO    264      // f32 stage stride (epilogue)

// ---- fp16 weight scratch layout (row-major [N][K]) ----
// WIN  [256][128]  (W_in zero-padded K66->128)
// WRZ  2 gates x [256][512]  rows = [W_ih_g | W_hh_g]
// WIHN [256][256], WHHN [256][256], WO1 [256][256], WO2 [64][256]
#define OFF_WIN  0
#define OFF_WRZ  (OFF_WIN  + 256 * 128)        // 32768
#define OFF_WIHN (OFF_WRZ  + 2 * 256 * 512)    // 294912
#define OFF_WHHN (OFF_WIHN + 256 * 256)        // 360448
#define OFF_WO1  (OFF_WHHN + 256 * 256)        // 425984
#define OFF_WO2  (OFF_WO1  + 256 * 256)        // 491520
#define W_TOTAL  (OFF_WO2  + 64 * 256)         // 507904

__device__ __align__(16) __half g_W[W_TOTAL];

// ---- smem byte offsets ----
#define OFF_A   0                    // 64 x 520 x 2B = 66560
#define OFF_W   66560                // 4 stages x (256 rows x 144B) = 147456
#define WSTAGE  36864
#define SMEM_TOTAL (66560 + 4 * WSTAGE)   // 214016
#define OFF_TO  OFF_W                // epilogue f32 staging (64x264x4 fits)

__device__ __forceinline__ uint32_t smem_to_u32(const void* p) {
    uint32_t a;
    asm("{ .reg .u64 t; cvta.to.shared.u64 t, %1; cvt.u32.u64 %0, t; }"
        : "=r"(a) : "l"(p));
    return a;
}
__device__ __forceinline__ void ldsm4(uint32_t* r, uint32_t addr) {
    asm volatile("ldmatrix.sync.aligned.m8n8.x4.shared.b16 {%0,%1,%2,%3}, [%4];"
                 : "=r"(r[0]), "=r"(r[1]), "=r"(r[2]), "=r"(r[3]) : "r"(addr));
}
__device__ __forceinline__ void mma16816(float* d, const uint32_t* a, const uint32_t* b) {
    asm volatile("mma.sync.aligned.m16n8k16.row.col.f32.f16.f16.f32 "
                 "{%0,%1,%2,%3}, {%4,%5,%6,%7}, {%8,%9}, {%0,%1,%2,%3};"
                 : "+f"(d[0]), "+f"(d[1]), "+f"(d[2]), "+f"(d[3])
                 : "r"(a[0]), "r"(a[1]), "r"(a[2]), "r"(a[3]),
                   "r"(b[0]), "r"(b[1]));
}
__device__ __forceinline__ uint32_t pack2h(float x, float y) {
    __half2 h = __floats2half2_rn(x, y);
    return *reinterpret_cast<uint32_t*>(&h);
}
__device__ __forceinline__ float sigm(float x) { return 1.0f / (1.0f + __expf(-x)); }

// ======================= weight conversion kernel ===========================
__global__ void wconv_kernel(const float* __restrict__ W_in,
                             const float* __restrict__ W_ih,
                             const float* __restrict__ W_hh,
                             const float* __restrict__ W_o1,
                             const float* __restrict__ W_o2) {
    for (long i = (long)blockIdx.x * blockDim.x + threadIdx.x; i < W_TOTAL;
         i += (long)gridDim.x * blockDim.x) {
        float v;
        if (i < OFF_WRZ) {                       // WIN
            long r = i >> 7, c = i & 127;
            v = (c < 66) ? W_in[r * 66 + c] : 0.0f;
        } else if (i < OFF_WIHN) {               // WRZ (gate 0 = r, 1 = z)
            long j = i - OFF_WRZ, g = j >> 17, jj = j & 131071;
            long n = jj >> 9, k = jj & 511;
            v = (k < 256) ? W_ih[(g * 256 + n) * 256 + k]
                          : W_hh[(g * 256 + n) * 256 + (k - 256)];
        } else if (i < OFF_WHHN) {               // W_ih gate n
            long j = i - OFF_WIHN, n = j >> 8, k = j & 255;
            v = W_ih[(512 + n) * 256 + k];
        } else if (i < OFF_WO1) {                // W_hh gate n
            long j = i - OFF_WHHN, n = j >> 8, k = j & 255;
            v = W_hh[(512 + n) * 256 + k];
        } else if (i < OFF_WO2)   v = W_o1[i - OFF_WO1];
        else                      v = W_o2[i - OFF_WO2];
        g_W[i] = __float2half_rn(v);
    }
}

// ---------------------------------------------------------------------------
// acc[2 mi][4 ni][4] += A(fp16 smem, byte offset offA) @ W(fp16 global)^T
// 64-col K-chunks via 4-stage cp.async pipeline (up to 3 in flight).
// 16 warps, warp (warp_m, warp_n0): rows warp_m*32..+32, cols warp_n0..+32.
// NR = weight rows (256 or 64). Stage rows are 144B (128B data + 16B pad).
// ---------------------------------------------------------------------------
template <int NR>
__device__ void gemm_mma(float acc[2][4][4], uint32_t sb, uint32_t offA,
                         const __half* __restrict__ Wg, int ldw, int nchunks,
                         int tid, int lane, int warp_m, int warp_n0)
{
    constexpr int TOT   = NR * 8;                 // 16B transfers per chunk
    constexpr int NITER = (TOT + THREADS - 1) / THREADS;

    auto issue = [&](int c) {
        uint32_t base = sb + OFF_W + (uint32_t)(c & 3) * WSTAGE;
        #pragma unroll
        for (int it = 0; it < NITER; ++it) {
            int idx = tid + THREADS * it;
            if ((TOT % THREADS == 0) || (idx < TOT)) {
                int row = idx >> 3, q = idx & 7;
                const __half* src = Wg + (long)row * ldw + c * 64 + q * 8;
                uint32_t dst = base + row * 144 + q * 16;
                asm volatile("cp.async.ca.shared.global [%0], [%1], 16;"
                             :: "r"(dst), "l"(src));
            }
        }
        asm volatile("cp.async.commit_group;" ::: "memory");
    };

    issue(0);
    if (nchunks > 1) issue(1);
    if (nchunks > 2) issue(2);
    for (int c = 0; c < nchunks; ++c) {
        int w = nchunks - 1 - c;                  // groups allowed pending
        if (w >= 2)      asm volatile("cp.async.wait_group 2;" ::: "memory");
        else if (w == 1) asm volatile("cp.async.wait_group 1;" ::: "memory");
        else             asm volatile("cp.async.wait_group 0;" ::: "memory");
        __syncthreads();                // chunk c visible; chunk c-1 compute done
        if (c + 3 < nchunks) issue(c + 3);        // buffer (c-1)&3, safe now

        const uint32_t wb = sb + OFF_W + (uint32_t)(c & 3) * WSTAGE;
        if (warp_n0 < NR) {
            const int mat = lane >> 3, r = lane & 7;
            #pragma unroll
            for (int ks = 0; ks < 4; ++ks) {
                uint32_t a[2][4], b[2][4];
                #pragma unroll
                for (int mi = 0; mi < 2; ++mi) {
                    int row = warp_m * 32 + mi * 16 + (mat & 1) * 8 + r;
                    int col = c * 64 + ks * 16 + (mat >> 1) * 8;
                    ldsm4(a[mi], sb + offA + (uint32_t)(row * LDA + col) * 2);
                }
                #pragma unroll
                for (int np = 0; np < 2; ++np) {
                    int n  = warp_n0 + (2 * np + (mat >> 1)) * 8 + r;
                    int kc = ks * 16 + (mat & 1) * 8;
                    ldsm4(b[np], wb + (uint32_t)(n * 144 + kc * 2));
                }
                #pragma unroll
                for (int np = 0; np < 2; ++np)
                    #pragma unroll
                    for (int hf = 0; hf < 2; ++hf)
                        #pragma unroll
                        for (int mi = 0; mi < 2; ++mi)
                            mma16816(acc[mi][2 * np + hf], a[mi], b[np] + 2 * hf);
            }
        }
    }
    __syncthreads();   // all mma reads of smem done before caller reuses tiles
}

__device__ __forceinline__ void zero_acc(float a[2][4][4]) {
    #pragma unroll
    for (int i = 0; i < 2; ++i)
        #pragma unroll
        for (int j = 0; j < 4; ++j)
            #pragma unroll
            for (int k = 0; k < 4; ++k) a[i][j][k] = 0.0f;
}

__global__ __launch_bounds__(THREADS, 1)
void ldm_kernel(const float* __restrict__ z, const float* __restrict__ action,
                const float* __restrict__ hidden,
                const float* __restrict__ b_in,
                const float* __restrict__ b_ih, const float* __restrict__ b_hh,
                const float* __restrict__ b_o1, const float* __restrict__ b_o2,
                float* __restrict__ out_z, float* __restrict__ out_h)
{
    extern __shared__ char sm[];
    const uint32_t sb = smem_to_u32(sm);
    const int tid = threadIdx.x, lane = tid & 31, warp = tid >> 5;
    const int warp_m = warp & 1, warp_n0 = (warp >> 1) * 32;
    const int gid = lane >> 2, tig = lane & 3;
    const long row0 = (long)blockIdx.x * TM;

    __half* A = (__half*)(sm + OFF_A);

    // ---- init: X cols 0..127 = [z|a|0] (128..255 filled by P0),
    //            H cols 256..511 = hidden ----
    for (int i = tid; i < TM * 128; i += THREADS) {
        int r = i >> 7, c = i & 127;
        float v = 0.0f;
        if (c < 64)      v = z[(row0 + r) * 64 + c];
        else if (c < 66) v = action[(row0 + r) * 2 + (c - 64)];
        A[r * LDA + c] = __float2half_rn(v);
    }
    for (int i = tid; i < TM * 256; i += THREADS) {
        int r = i >> 8, c = i & 255;
        A[r * LDA + 256 + c] = __float2half_rn(hidden[(row0 + r) * 256 + c]);
    }
    __syncthreads();

    float acc[2][4][4], hn[2][4][4];

    // ================= P0: x = relu([z|a] @ W_in^T + b_in) -> X cols ========
    zero_acc(acc);
    gemm_mma<256>(acc, sb, OFF_A, g_W + OFF_WIN, 128, 2,
                  tid, lane, warp_m, warp_n0);
    #pragma unroll
    for (int mi = 0; mi < 2; ++mi)
        #pragma unroll
        for (int ni = 0; ni < 4; ++ni) {
            int col0 = warp_n0 + ni * 8 + tig * 2;
            int ra = warp_m * 32 + mi * 16 + gid, rb = ra + 8;
            float v0 = fmaxf(acc[mi][ni][0] + b_in[col0],     0.0f);
            float v1 = fmaxf(acc[mi][ni][1] + b_in[col0 + 1], 0.0f);
            float v2 = fmaxf(acc[mi][ni][2] + b_in[col0],     0.0f);
            float v3 = fmaxf(acc[mi][ni][3] + b_in[col0 + 1], 0.0f);
            *(uint32_t*)(sm + OFF_A + (ra * LDA + col0) * 2) = pack2h(v0, v1);
            *(uint32_t*)(sm + OFF_A + (rb * LDA + col0) * 2) = pack2h(v2, v3);
        }
    __syncthreads();

    // ================= P1: hn = h @ Whh_n^T + b_hh_n ========================
    zero_acc(acc);
    gemm_mma<256>(acc, sb, OFF_A + 512, g_W + OFF_WHHN, 256, 4,
                  tid, lane, warp_m, warp_n0);
    #pragma unroll
    for (int mi = 0; mi < 2; ++mi)
        #pragma unroll
        for (int ni = 0; ni < 4; ++ni) {
            int col0 = warp_n0 + ni * 8 + tig * 2;
            hn[mi][ni][0] = acc[mi][ni][0] + b_hh[512 + col0];
            hn[mi][ni][1] = acc[mi][ni][1] + b_hh[512 + col0 + 1];
            hn[mi][ni][2] = acc[mi][ni][2] + b_hh[512 + col0];
            hn[mi][ni][3] = acc[mi][ni][3] + b_hh[512 + col0 + 1];
        }

    // ================= P2: r = sigm([X|H] @ WRZ_r^T + b); hn *= r ===========
    zero_acc(acc);
    gemm_mma<256>(acc, sb, OFF_A, g_W + OFF_WRZ, 512, 8,
                  tid, lane, warp_m, warp_n0);
    #pragma unroll
    for (int mi = 0; mi < 2; ++mi)
        #pragma unroll
        for (int ni = 0; ni < 4; ++ni) {
            int col0 = warp_n0 + ni * 8 + tig * 2;
            float b0 = b_ih[col0] + b_hh[col0];
            float b1 = b_ih[col0 + 1] + b_hh[col0 + 1];
            hn[mi][ni][0] *= sigm(acc[mi][ni][0] + b0);
            hn[mi][ni][1] *= sigm(acc[mi][ni][1] + b1);
            hn[mi][ni][2] *= sigm(acc[mi][ni][2] + b0);
            hn[mi][ni][3] *= sigm(acc[mi][ni][3] + b1);
        }

    // ================= P3: hn = tanh(x@Wih_n + b + r*hn) ====================
    zero_acc(acc);
    gemm_mma<256>(acc, sb, OFF_A, g_W + OFF_WIHN, 256, 4,
                  tid, lane, warp_m, warp_n0);
    #pragma unroll
    for (int mi = 0; mi < 2; ++mi)
        #pragma unroll
        for (int ni = 0; ni < 4; ++ni) {
            int col0 = warp_n0 + ni * 8 + tig * 2;
            hn[mi][ni][0] = tanhf(acc[mi][ni][0] + b_ih[512 + col0]     + hn[mi][ni][0]);
            hn[mi][ni][1] = tanhf(acc[mi][ni][1] + b_ih[512 + col0 + 1] + hn[mi][ni][1]);
            hn[mi][ni][2] = tanhf(acc[mi][ni][2] + b_ih[512 + col0]     + hn[mi][ni][2]);
            hn[mi][ni][3] = tanhf(acc[mi][ni][3] + b_ih[512 + col0 + 1] + hn[mi][ni][3]);
        }

    // ================= P4: zg = sigm([X|H] @ WRZ_z^T + b); h_new ============
    zero_acc(acc);
    gemm_mma<256>(acc, sb, OFF_A, g_W + OFF_WRZ + 256 * 512, 512, 8,
                  tid, lane, warp_m, warp_n0);
    {
        float* TO = (float*)(sm + OFF_TO);
        #pragma unroll
        for (int mi = 0; mi < 2; ++mi)
            #pragma unroll
            for (int ni = 0; ni < 4; ++ni) {
                int col0 = warp_n0 + ni * 8 + tig * 2;
                int ra = warp_m * 32 + mi * 16 + gid, rb = ra + 8;
                #pragma unroll
                for (int cc = 0; cc < 4; ++cc) {
                    int row = (cc < 2) ? ra : rb;
                    int col = col0 + (cc & 1);
                    float zg = sigm(acc[mi][ni][cc] + b_ih[256 + col] + b_hh[256 + col]);
                    float h  = hidden[(row0 + row) * 256 + col];   // full precision
                    TO[row * LDTO + col] = (1.0f - zg) * hn[mi][ni][cc] + zg * h;
                }
            }
        __syncthreads();
        // coalesced out_h store + X tile refill with h_new
        for (int i = tid; i < TM * 256; i += THREADS) {
            int r = i >> 8, c = i & 255;
            float v = TO[r * LDTO + c];
            out_h[(row0 + r) * 256 + c] = v;
            A[r * LDA + c] = __float2half_rn(v);
        }
        __syncthreads();
    }

    // ================= P5: y = relu(h_new @ W_o1^T + b_o1) -> H cols ========
    zero_acc(acc);
    gemm_mma<256>(acc, sb, OFF_A, g_W + OFF_WO1, 256, 4,
                  tid, lane, warp_m, warp_n0);
    #pragma unroll
    for (int mi = 0; mi < 2; ++mi)
        #pragma unroll
        for (int ni = 0; ni < 4; ++ni) {
            int col0 = warp_n0 + ni * 8 + tig * 2;
            int ra = warp_m * 32 + mi * 16 + gid, rb = ra + 8;
            float v0 = fmaxf(acc[mi][ni][0] + b_o1[col0],     0.0f);
            float v1 = fmaxf(acc[mi][ni][1] + b_o1[col0 + 1], 0.0f);
            float v2 = fmaxf(acc[mi][ni][2] + b_o1[col0],     0.0f);
            float v3 = fmaxf(acc[mi][ni][3] + b_o1[col0 + 1], 0.0f);
            *(uint32_t*)(sm + OFF_A + (ra * LDA + 256 + col0) * 2) = pack2h(v0, v1);
            *(uint32_t*)(sm + OFF_A + (rb * LDA + 256 + col0) * 2) = pack2h(v2, v3);
        }
    __syncthreads();

    // ================= P6: z_next = y @ W_o2^T + b_o2 (N=64) ================
    zero_acc(acc);
    gemm_mma<64>(acc, sb, OFF_A + 512, g_W + OFF_WO2, 256, 4,
                 tid, lane, warp_m, warp_n0);
    {
        float* TO = (float*)(sm + OFF_TO);
        if (warp_n0 < 64) {
            #pragma unroll
            for (int mi = 0; mi < 2; ++mi)
                #pragma unroll
                for (int ni = 0; ni < 4; ++ni) {
                    int col0 = warp_n0 + ni * 8 + tig * 2;
                    int ra = warp_m * 32 + mi * 16 + gid, rb = ra + 8;
                    TO[ra * 68 + col0]     = acc[mi][ni][0] + b_o2[col0];
                    TO[ra * 68 + col0 + 1] = acc[mi][ni][1] + b_o2[col0 + 1];
                    TO[rb * 68 + col0]     = acc[mi][ni][2] + b_o2[col0];
                    TO[rb * 68 + col0 + 1] = acc[mi][ni][3] + b_o2[col0 + 1];
                }
        }
        __syncthreads();
        for (int i = tid; i < TM * 64; i += THREADS) {
            int r = i >> 6, c = i & 63;
            out_z[(row0 + r) * 64 + c] = TO[r * 68 + c];
        }
    }
}

// ============================== launch ======================================

extern "C" void kernel_launch(void* const* d_in, const int* in_sizes, int n_in,
                              void* d_out, int out_size) {
    const float* z      = (const float*)d_in[0];
    const float* action = (const float*)d_in[1];
    const float* hidden = (const float*)d_in[2];
    const float* W_in   = (const float*)d_in[3];
    const float* b_in   = (const float*)d_in[4];
    const float* W_ih   = (const float*)d_in[5];
    const float* W_hh   = (const float*)d_in[6];
    const float* b_ih   = (const float*)d_in[7];
    const float* b_hh   = (const float*)d_in[8];
    const float* W_o1   = (const float*)d_in[9];
    const float* b_o1   = (const float*)d_in[10];
    const float* W_o2   = (const float*)d_in[11];
    const float* b_o2   = (const float*)d_in[12];

    float* out_z = (float*)d_out;                       // [B, 64]
    float* out_h = (float*)d_out + (long)BATCH * 64;    // [B, 256]

    cudaFuncSetAttribute(ldm_kernel,
                         cudaFuncAttributeMaxDynamicSharedMemorySize, SMEM_TOTAL);

    wconv_kernel<<<256, 256>>>(W_in, W_ih, W_hh, W_o1, W_o2);
    dim3 grid(BATCH / TM);
    ldm_kernel<<<grid, THREADS, SMEM_TOTAL>>>(
        z, action, hidden, b_in, b_ih, b_hh, b_o1, b_o2, out_z, out_h);
}